// round 3
// baseline (speedup 1.0000x reference)
#include <cuda_runtime.h>
#include <cuda_fp16.h>
#include <cstddef>

#define NB     2
#define N_IN   163842
#define N_OUT  40962
#define CDIM   128
#define KCAND  7

// Scratch (static device globals — no runtime allocation).
__device__ float  g_down[(size_t)NB * N_OUT * CDIM];
__device__ float  g_denom[N_OUT];
__device__ __half g_down_h[(size_t)NB * N_OUT * CDIM];

// ---------------------------------------------------------------------------
// Kernel 0: zero f32 scratch + denom (graph-replayed every run).
// ---------------------------------------------------------------------------
__global__ void zero_kernel() {
    const size_t total4 = (size_t)NB * N_OUT * CDIM / 4;  // float4 count
    const size_t stride = (size_t)gridDim.x * blockDim.x;
    for (size_t i = (size_t)blockIdx.x * blockDim.x + threadIdx.x;
         i < total4; i += stride) {
        reinterpret_cast<float4*>(g_down)[i] = make_float4(0.f, 0.f, 0.f, 0.f);
    }
    size_t t = (size_t)blockIdx.x * blockDim.x + threadIdx.x;
    if (t < N_OUT) g_denom[t] = 0.f;
}

// ---------------------------------------------------------------------------
// Kernel 1: scatter-add  down[b, parent[n], :] += omega[n] * x[b, n, :]
//           denom[parent[n]] += omega[n]
// One warp per input row n; lane covers 4 channels; red.global.add.v4.f32.
// ---------------------------------------------------------------------------
__global__ void scatter_kernel(const float* __restrict__ x,
                               const float* __restrict__ omega,
                               const int*   __restrict__ parent) {
    const int warp = (int)(((size_t)blockIdx.x * blockDim.x + threadIdx.x) >> 5);
    const int lane = threadIdx.x & 31;
    if (warp >= N_IN) return;

    const int   p  = parent[warp];
    const float om = omega[warp];

#pragma unroll
    for (int b = 0; b < NB; ++b) {
        const float4* xrow =
            reinterpret_cast<const float4*>(x + ((size_t)b * N_IN + warp) * CDIM);
        float4 v = xrow[lane];
        v.x *= om; v.y *= om; v.z *= om; v.w *= om;
        float* dst = g_down + ((size_t)b * N_OUT + p) * CDIM + lane * 4;
        asm volatile("red.global.add.v4.f32 [%0], {%1, %2, %3, %4};"
                     :: "l"(dst), "f"(v.x), "f"(v.y), "f"(v.z), "f"(v.w)
                     : "memory");
    }
    if (lane == 0) {
        atomicAdd(&g_denom[p], om);
    }
}

// ---------------------------------------------------------------------------
// Kernel 2: convert f32 scratch -> fp16 with 1/denom pre-folded.
//   down_h[b,p,c] = (half)( down[b,p,c] / max(denom[p], 1e-8) )
// One warp per output row p; lane covers 4 channels; both batches.
// ---------------------------------------------------------------------------
__global__ void convert_kernel() {
    const int warp = (int)(((size_t)blockIdx.x * blockDim.x + threadIdx.x) >> 5);
    const int lane = threadIdx.x & 31;
    if (warp >= N_OUT) return;

    const float inv_den = 1.f / fmaxf(g_denom[warp], 1e-8f);

#pragma unroll
    for (int b = 0; b < NB; ++b) {
        const size_t base = ((size_t)b * N_OUT + warp) * CDIM;
        float4 v = reinterpret_cast<const float4*>(g_down + base)[lane];
        v.x *= inv_den; v.y *= inv_den; v.z *= inv_den; v.w *= inv_den;
        __half2 h0 = __floats2half2_rn(v.x, v.y);
        __half2 h1 = __floats2half2_rn(v.z, v.w);
        // 8-byte store of 4 halves
        uint2 packed;
        packed.x = *reinterpret_cast<unsigned int*>(&h0);
        packed.y = *reinterpret_cast<unsigned int*>(&h1);
        reinterpret_cast<uint2*>(g_down_h + base)[lane] = packed;
    }
}

// ---------------------------------------------------------------------------
// Kernel 3: gather. One warp per input row n; lanes 0-15 handle b=0,
// lanes 16-31 handle b=1. Each lane loads 16B = 8 halves per candidate,
// so a 16-lane half-warp covers the full 256B fp16 row (fully coalesced).
//   out[b,n,:] = sum_k wk[k] * down_h[b, cand[k], :]   (denom pre-folded)
// ---------------------------------------------------------------------------
__global__ void gather_kernel(const float* __restrict__ delta,
                              const float* __restrict__ mask,
                              const int*   __restrict__ cand,
                              float*       __restrict__ out) {
    const int warp = (int)(((size_t)blockIdx.x * blockDim.x + threadIdx.x) >> 5);
    const int lane = threadIdx.x & 31;
    if (warp >= N_IN) return;

    const int sub = lane >> 4;   // batch index
    const int li  = lane & 15;   // 16B slot within row

    const float INV2S2 = 3.125f;  // 1 / (2 * 0.4^2)

    float wk[KCAND];
    int   idx[KCAND];
    float wsum = 0.f;
#pragma unroll
    for (int k = 0; k < KCAND; ++k) {
        const size_t o = (size_t)warp * KCAND + k;
        float d = delta[o];          // broadcast within warp
        float m = mask[o];
        idx[k]  = cand[o];
        wk[k]   = __expf(-d * d * INV2S2) * m;
        wsum   += wk[k];
    }
    const float inv_wsum = 1.f / fmaxf(wsum, 1e-8f);
#pragma unroll
    for (int k = 0; k < KCAND; ++k) wk[k] *= inv_wsum;

    float acc[8];
#pragma unroll
    for (int i = 0; i < 8; ++i) acc[i] = 0.f;

#pragma unroll
    for (int k = 0; k < KCAND; ++k) {
        const __half* row = g_down_h + ((size_t)sub * N_OUT + idx[k]) * CDIM;
        // 16 bytes = 8 halves per lane
        const float4 raw = __ldg(reinterpret_cast<const float4*>(row) + li);
        const __half2* h2 = reinterpret_cast<const __half2*>(&raw);
        const float w = wk[k];
#pragma unroll
        for (int j = 0; j < 4; ++j) {
            float2 f = __half22float2(h2[j]);
            acc[2 * j]     = fmaf(w, f.x, acc[2 * j]);
            acc[2 * j + 1] = fmaf(w, f.y, acc[2 * j + 1]);
        }
    }

    float* dst = out + ((size_t)sub * N_IN + warp) * CDIM + li * 8;
    reinterpret_cast<float4*>(dst)[0] = make_float4(acc[0], acc[1], acc[2], acc[3]);
    reinterpret_cast<float4*>(dst)[1] = make_float4(acc[4], acc[5], acc[6], acc[7]);
}

// ---------------------------------------------------------------------------
// Launcher. Input order: x, omega, delta, cand_mask, parent_idx, cand_idx.
// Output: float32 (B, N_IN, C).
// ---------------------------------------------------------------------------
extern "C" void kernel_launch(void* const* d_in, const int* in_sizes, int n_in,
                              void* d_out, int out_size) {
    const float* x      = (const float*)d_in[0];
    const float* omega  = (const float*)d_in[1];
    const float* delta  = (const float*)d_in[2];
    const float* mask   = (const float*)d_in[3];
    const int*   parent = (const int*)d_in[4];
    const int*   cand   = (const int*)d_in[5];
    float*       out    = (float*)d_out;

    (void)in_sizes; (void)n_in; (void)out_size;

    // Zero scratch (grid-stride)
    {
        const size_t total4 = (size_t)NB * N_OUT * CDIM / 4;
        const int threads = 256;
        int blocks = (int)((total4 + threads - 1) / threads);
        zero_kernel<<<blocks, threads>>>();
    }
    // Scatter pool (f32 atomics)
    {
        const int threads = 256;  // 8 warps / block
        const int blocks  = (N_IN + 8 - 1) / 8;
        scatter_kernel<<<blocks, threads>>>(x, omega, parent);
    }
    // f32 -> fp16 with denom folded
    {
        const int threads = 256;
        const int blocks  = (N_OUT + 8 - 1) / 8;
        convert_kernel<<<blocks, threads>>>();
    }
    // Gather + weight (fp16 reads, f32 accumulate)
    {
        const int threads = 256;
        const int blocks  = (N_IN + 8 - 1) / 8;
        gather_kernel<<<blocks, threads>>>(delta, mask, cand, out);
    }
}

// round 5
// speedup vs baseline: 1.6258x; 1.6258x over previous
#include <cuda_runtime.h>
#include <cuda_fp16.h>
#include <cstddef>

#define NB     2
#define N_IN   163842
#define N_OUT  40962
#define CDIM   128
#define KCAND  7

// Scratch (static device globals — no runtime allocation).
// Pooled weighted sums accumulate directly in fp16 (atomic f16x2 reductions).
__device__ __half g_down_h[(size_t)NB * N_OUT * CDIM];   // 21 MB
__device__ float  g_denom[N_OUT];

// ---------------------------------------------------------------------------
// Kernel 0: zero fp16 scratch + denom (graph-replayed every run). Grid-stride.
// ---------------------------------------------------------------------------
__global__ void zero_kernel() {
    const size_t total16 = (size_t)NB * N_OUT * CDIM * sizeof(__half) / 16;
    const size_t stride  = (size_t)gridDim.x * blockDim.x;
    for (size_t i = (size_t)blockIdx.x * blockDim.x + threadIdx.x;
         i < total16; i += stride) {
        uint4 z; z.x = 0u; z.y = 0u; z.z = 0u; z.w = 0u;
        reinterpret_cast<uint4*>(g_down_h)[i] = z;
    }
    const size_t t = (size_t)blockIdx.x * blockDim.x + threadIdx.x;
    if (t < N_OUT) g_denom[t] = 0.f;
}

// ---------------------------------------------------------------------------
// Kernel 1: scatter-add in fp16:
//   down_h[b, parent[n], :] += fp16(omega[n] * x[b, n, :])
//   denom[parent[n]]        += omega[n]
// One warp per input row n. Lanes 0-15 handle b=0, lanes 16-31 handle b=1.
// Each lane covers 8 channels: 2x LDG.128 f32, 4x pack to f16x2, one
// red.global.add.noftz.v4.f16x2 (16B) => 32 REDG lane-ops per warp total.
// ---------------------------------------------------------------------------
__global__ void scatter_kernel(const float* __restrict__ x,
                               const float* __restrict__ omega,
                               const int*   __restrict__ parent) {
    const int warp = (int)(((size_t)blockIdx.x * blockDim.x + threadIdx.x) >> 5);
    const int lane = threadIdx.x & 31;
    if (warp >= N_IN) return;

    const int   p  = parent[warp];   // broadcast
    const float om = omega[warp];    // broadcast

    const int sub = lane >> 4;       // batch
    const int li  = lane & 15;       // 16B slot (8 channels) within the row

    const float4* xr =
        reinterpret_cast<const float4*>(x + ((size_t)sub * N_IN + warp) * CDIM)
        + li * 2;
    float4 a = xr[0];
    float4 b = xr[1];
    a.x *= om; a.y *= om; a.z *= om; a.w *= om;
    b.x *= om; b.y *= om; b.z *= om; b.w *= om;

    __half2 h0 = __floats2half2_rn(a.x, a.y);
    __half2 h1 = __floats2half2_rn(a.z, a.w);
    __half2 h2 = __floats2half2_rn(b.x, b.y);
    __half2 h3 = __floats2half2_rn(b.z, b.w);

    __half* dst = g_down_h + ((size_t)sub * N_OUT + p) * CDIM + li * 8;
    asm volatile("red.global.add.noftz.v4.f16x2 [%0], {%1, %2, %3, %4};"
                 :: "l"(dst),
                    "r"(*reinterpret_cast<unsigned*>(&h0)),
                    "r"(*reinterpret_cast<unsigned*>(&h1)),
                    "r"(*reinterpret_cast<unsigned*>(&h2)),
                    "r"(*reinterpret_cast<unsigned*>(&h3))
                 : "memory");

    if (lane == 0) {
        atomicAdd(&g_denom[p], om);
    }
}

// ---------------------------------------------------------------------------
// Kernel 2: gather. One warp per input row n.
// Weight computation is lane-parallel: lanes 0-6 each handle one candidate k
// (4 scalar LDGs + 1 MUFU per WARP instead of 21 LDGs + 7 MUFUs), width-8
// shuffle reduction for the weight sum, denom folded into the weight, then
// full-warp shuffles distribute (w_k, idx_k).
// Row accumulation: lanes 0-15 -> b=0, lanes 16-31 -> b=1; each lane loads
// 16B = 8 halves per candidate (7 LDG.128 per warp covering both batches),
// f32 accumulate, 2x STG.128 f32 out per lane.
// ---------------------------------------------------------------------------
__global__ void gather_kernel(const float* __restrict__ delta,
                              const float* __restrict__ mask,
                              const int*   __restrict__ cand,
                              float*       __restrict__ out) {
    const int warp = (int)(((size_t)blockIdx.x * blockDim.x + threadIdx.x) >> 5);
    const int lane = threadIdx.x & 31;
    if (warp >= N_IN) return;

    const float INV2S2 = 3.125f;  // 1 / (2 * 0.4^2)

    // ---- lanes 0-6: per-candidate weight ----
    float w = 0.f;
    int   c = 0;
    if (lane < KCAND) {
        const size_t o = (size_t)warp * KCAND + lane;
        const float d = delta[o];
        const float m = mask[o];
        c = cand[o];
        w = __expf(-d * d * INV2S2) * m;
    }
    // sum over lanes 0-7 (lane 7 contributes 0), width-8 butterfly
    float s = w;
    s += __shfl_down_sync(0xffffffffu, s, 4, 8);
    s += __shfl_down_sync(0xffffffffu, s, 2, 8);
    s += __shfl_down_sync(0xffffffffu, s, 1, 8);
    s  = __shfl_sync(0xffffffffu, s, 0, 8);   // lanes 0-7 get total

    if (lane < KCAND) {
        const float den = fmaxf(__ldg(&g_denom[c]), 1e-8f);
        w = w / (fmaxf(s, 1e-8f) * den);
    }

    // ---- row accumulation ----
    const int sub = lane >> 4;
    const int li  = lane & 15;

    float acc[8];
#pragma unroll
    for (int i = 0; i < 8; ++i) acc[i] = 0.f;

#pragma unroll
    for (int k = 0; k < KCAND; ++k) {
        const float wk = __shfl_sync(0xffffffffu, w, k);
        const int   ik = __shfl_sync(0xffffffffu, c, k);
        const float4 raw = __ldg(reinterpret_cast<const float4*>(
            g_down_h + ((size_t)sub * N_OUT + ik) * CDIM) + li);
        const __half2* h2 = reinterpret_cast<const __half2*>(&raw);
#pragma unroll
        for (int j = 0; j < 4; ++j) {
            const float2 f = __half22float2(h2[j]);
            acc[2 * j]     = fmaf(wk, f.x, acc[2 * j]);
            acc[2 * j + 1] = fmaf(wk, f.y, acc[2 * j + 1]);
        }
    }

    float* dst = out + ((size_t)sub * N_IN + warp) * CDIM + li * 8;
    reinterpret_cast<float4*>(dst)[0] = make_float4(acc[0], acc[1], acc[2], acc[3]);
    reinterpret_cast<float4*>(dst)[1] = make_float4(acc[4], acc[5], acc[6], acc[7]);
}

// ---------------------------------------------------------------------------
// Launcher. Input order: x, omega, delta, cand_mask, parent_idx, cand_idx.
// Output: float32 (B, N_IN, C).
// ---------------------------------------------------------------------------
extern "C" void kernel_launch(void* const* d_in, const int* in_sizes, int n_in,
                              void* d_out, int out_size) {
    const float* x      = (const float*)d_in[0];
    const float* omega  = (const float*)d_in[1];
    const float* delta  = (const float*)d_in[2];
    const float* mask   = (const float*)d_in[3];
    const int*   parent = (const int*)d_in[4];
    const int*   cand   = (const int*)d_in[5];
    float*       out    = (float*)d_out;

    (void)in_sizes; (void)n_in; (void)out_size;

    // Zero fp16 scratch + denom
    {
        const size_t total16 = (size_t)NB * N_OUT * CDIM * sizeof(__half) / 16;
        const int threads = 256;
        const int blocks  = (int)((total16 + threads - 1) / threads);
        zero_kernel<<<blocks, threads>>>();
    }
    // Scatter pool (fp16 vector reductions)
    {
        const int threads = 256;  // 8 warps / block
        const int blocks  = (N_IN + 8 - 1) / 8;
        scatter_kernel<<<blocks, threads>>>(x, omega, parent);
    }
    // Gather + weight (fp16 reads, f32 accumulate)
    {
        const int threads = 256;
        const int blocks  = (N_IN + 8 - 1) / 8;
        gather_kernel<<<blocks, threads>>>(delta, mask, cand, out);
    }
}

// round 8
// speedup vs baseline: 1.7635x; 1.0847x over previous
#include <cuda_runtime.h>
#include <cuda_fp16.h>
#include <cstddef>

#define NB     2
#define N_IN   163842
#define N_OUT  40962
#define CDIM   128
#define KCAND  7

// Scratch (static device globals — no runtime allocation).
// Pooled weighted sums accumulate directly in fp16 (atomic f16x2 reductions).
__device__ __half g_down_h[(size_t)NB * N_OUT * CDIM];   // 21 MB
__device__ float  g_denom[N_OUT];

// ---------------------------------------------------------------------------
// Kernel 0: zero fp16 scratch + denom (graph-replayed every run). Grid-stride.
// ---------------------------------------------------------------------------
__global__ void __launch_bounds__(256) zero_kernel() {
    const size_t total16 = (size_t)NB * N_OUT * CDIM * sizeof(__half) / 16;
    const size_t stride  = (size_t)gridDim.x * blockDim.x;
    for (size_t i = (size_t)blockIdx.x * blockDim.x + threadIdx.x;
         i < total16; i += stride) {
        uint4 z; z.x = 0u; z.y = 0u; z.z = 0u; z.w = 0u;
        reinterpret_cast<uint4*>(g_down_h)[i] = z;
    }
    const size_t t = (size_t)blockIdx.x * blockDim.x + threadIdx.x;
    if (t < N_OUT) g_denom[t] = 0.f;
}

// ---------------------------------------------------------------------------
// Kernel 1: scatter-add in fp16:
//   down_h[b, parent[n], :] += fp16(omega[n] * x[b, n, :])
//   denom[parent[n]]        += omega[n]
// One warp per input row n. Lanes 0-15 handle b=0, lanes 16-31 handle b=1.
// Each lane covers 8 channels: 2x LDG.128 f32, 4x pack to f16x2, one
// red.global.add.noftz.v4.f16x2 (16B) => 32 REDG lane-ops per warp total.
// ---------------------------------------------------------------------------
__global__ void __launch_bounds__(256) scatter_kernel(
        const float* __restrict__ x,
        const float* __restrict__ omega,
        const int*   __restrict__ parent) {
    const int warp = (int)(((size_t)blockIdx.x * blockDim.x + threadIdx.x) >> 5);
    const int lane = threadIdx.x & 31;
    if (warp >= N_IN) return;

    const int   p  = parent[warp];   // broadcast
    const float om = omega[warp];    // broadcast

    const int sub = lane >> 4;       // batch
    const int li  = lane & 15;       // 16B slot (8 channels) within the row

    const float4* xr =
        reinterpret_cast<const float4*>(x + ((size_t)sub * N_IN + warp) * CDIM)
        + li * 2;
    float4 a = xr[0];
    float4 b = xr[1];
    a.x *= om; a.y *= om; a.z *= om; a.w *= om;
    b.x *= om; b.y *= om; b.z *= om; b.w *= om;

    __half2 h0 = __floats2half2_rn(a.x, a.y);
    __half2 h1 = __floats2half2_rn(a.z, a.w);
    __half2 h2 = __floats2half2_rn(b.x, b.y);
    __half2 h3 = __floats2half2_rn(b.z, b.w);

    __half* dst = g_down_h + ((size_t)sub * N_OUT + p) * CDIM + li * 8;
    asm volatile("red.global.add.noftz.v4.f16x2 [%0], {%1, %2, %3, %4};"
                 :: "l"(dst),
                    "r"(*reinterpret_cast<unsigned*>(&h0)),
                    "r"(*reinterpret_cast<unsigned*>(&h1)),
                    "r"(*reinterpret_cast<unsigned*>(&h2)),
                    "r"(*reinterpret_cast<unsigned*>(&h3))
                 : "memory");

    if (lane == 0) {
        atomicAdd(&g_denom[p], om);
    }
}

// ---------------------------------------------------------------------------
// Kernel 2: gather. One warp per input row n.
// Weights lane-parallel (lanes 0-6, one candidate each: 3 scalar LDG + 1 MUFU
// per warp), width-8 shuffle reduction, denom folded in, packed to half2.
// Row accumulation in fp16 via HFMA2 into TWO interleaved partial sums
// (k even -> accA, k odd -> accB; chains <= 4 deep), finalized in f32.
// Lanes 0-15 -> b=0, lanes 16-31 -> b=1; each lane loads 16B = 8 halves per
// candidate; loop body per lane per k = 1 LDG.128 + 4 HFMA2.
// ---------------------------------------------------------------------------
__global__ void __launch_bounds__(256) gather_kernel(
        const float* __restrict__ delta,
        const float* __restrict__ mask,
        const int*   __restrict__ cand,
        float*       __restrict__ out) {
    const int warp = (int)(((size_t)blockIdx.x * blockDim.x + threadIdx.x) >> 5);
    const int lane = threadIdx.x & 31;
    if (warp >= N_IN) return;

    const float INV2S2 = 3.125f;  // 1 / (2 * 0.4^2)

    // ---- lanes 0-6: per-candidate weight ----
    float w = 0.f;
    int   c = 0;
    if (lane < KCAND) {
        const size_t o = (size_t)warp * KCAND + lane;
        const float d = delta[o];
        const float m = mask[o];
        c = cand[o];
        w = __expf(-d * d * INV2S2) * m;
    }
    // sum over lanes 0-7 (lane 7 contributes 0), width-8 butterfly
    float s = w;
    s += __shfl_down_sync(0xffffffffu, s, 4, 8);
    s += __shfl_down_sync(0xffffffffu, s, 2, 8);
    s += __shfl_down_sync(0xffffffffu, s, 1, 8);
    s  = __shfl_sync(0xffffffffu, s, 0, 8);   // lanes 0-7 get total

    unsigned whbits = 0;
    if (lane < KCAND) {
        const float den = fmaxf(__ldg(&g_denom[c]), 1e-8f);
        float wf = w / (fmaxf(s, 1e-8f) * den);
        // Clamp: zero-parent outputs give wf ~ 1e8, which would become fp16
        // inf and produce inf*0 = NaN. Their rows are all-zero, so any finite
        // weight is exact. Real weights are <= ~3.
        wf = fminf(wf, 1000.0f);
        const __half2 wh = __float2half2_rn(wf);
        whbits = *reinterpret_cast<const unsigned*>(&wh);
    }

    // ---- row accumulation (fp16 HFMA2, two interleaved partials) ----
    const int sub = lane >> 4;
    const int li  = lane & 15;

    const __half2 hz = __float2half2_rn(0.f);
    __half2 accA[4] = {hz, hz, hz, hz};
    __half2 accB[4] = {hz, hz, hz, hz};

#pragma unroll
    for (int k = 0; k < KCAND; ++k) {
        const unsigned wb = __shfl_sync(0xffffffffu, whbits, k);
        const int      ik = __shfl_sync(0xffffffffu, c, k);
        const __half2  wh = *reinterpret_cast<const __half2*>(&wb);
        const float4 raw = __ldg(reinterpret_cast<const float4*>(
            g_down_h + ((size_t)sub * N_OUT + ik) * CDIM) + li);
        const __half2* h2 = reinterpret_cast<const __half2*>(&raw);
        if ((k & 1) == 0) {
#pragma unroll
            for (int j = 0; j < 4; ++j) accA[j] = __hfma2(h2[j], wh, accA[j]);
        } else {
#pragma unroll
            for (int j = 0; j < 4; ++j) accB[j] = __hfma2(h2[j], wh, accB[j]);
        }
    }

    // Finalize in f32: convert both partials, add, store.
    float res[8];
#pragma unroll
    for (int j = 0; j < 4; ++j) {
        const float2 a = __half22float2(accA[j]);
        const float2 b = __half22float2(accB[j]);
        res[2 * j]     = a.x + b.x;
        res[2 * j + 1] = a.y + b.y;
    }

    float* dst = out + ((size_t)sub * N_IN + warp) * CDIM + li * 8;
    reinterpret_cast<float4*>(dst)[0] = make_float4(res[0], res[1], res[2], res[3]);
    reinterpret_cast<float4*>(dst)[1] = make_float4(res[4], res[5], res[6], res[7]);
}

// ---------------------------------------------------------------------------
// Launcher. Input order: x, omega, delta, cand_mask, parent_idx, cand_idx.
// Output: float32 (B, N_IN, C).
// ---------------------------------------------------------------------------
extern "C" void kernel_launch(void* const* d_in, const int* in_sizes, int n_in,
                              void* d_out, int out_size) {
    const float* x      = (const float*)d_in[0];
    const float* omega  = (const float*)d_in[1];
    const float* delta  = (const float*)d_in[2];
    const float* mask   = (const float*)d_in[3];
    const int*   parent = (const int*)d_in[4];
    const int*   cand   = (const int*)d_in[5];
    float*       out    = (float*)d_out;

    (void)in_sizes; (void)n_in; (void)out_size;

    // Zero fp16 scratch + denom (kernel-based; known-good under graph capture)
    {
        const size_t total16 = (size_t)NB * N_OUT * CDIM * sizeof(__half) / 16;
        const int threads = 256;
        const int blocks  = (int)((total16 + threads - 1) / threads);
        zero_kernel<<<blocks, threads>>>();
    }
    // Scatter pool (fp16 vector reductions)
    {
        const int threads = 256;  // 8 warps / block
        const int blocks  = (N_IN + 8 - 1) / 8;
        scatter_kernel<<<blocks, threads>>>(x, omega, parent);
    }
    // Gather + weight (fp16 HFMA2 accumulate, f32 finalize)
    {
        const int threads = 256;
        const int blocks  = (N_IN + 8 - 1) / 8;
        gather_kernel<<<blocks, threads>>>(delta, mask, cand, out);
    }
}